// round 13
// baseline (speedup 1.0000x reference)
#include <cuda_runtime.h>
#include <cmath>

#define NB 128   // batch
#define NKE 64   // entities (K)
#define ND 128   // feature dim D
#define NS 128   // S
#define NL 2     // layers
#define MROWS (NB*NKE)   // 8192
#define SPITCH 132       // padded smem row stride (floats) for attn tiles
#define NCAT 512         // fused q|k|P|Q width
#define UTP 36           // transposed-tile row stride (floats), 32+4, mult of 4
#define NTILES (MROWS/32) // 256
#define PGRID 148        // persistent grid for fused_mlp

typedef unsigned long long u64;

// ---------------- scratch (static device arrays; no allocation) ----------------
__device__ float g_x[MROWS*ND];
__device__ float g_qkpq[MROWS*NCAT];          // 16 MB
__device__ float g_u[MROWS*ND];
__device__ float g_wcat[NL*ND*NCAT];          // per-layer fused weights

// ---------------- f32x2 packed helpers (Blackwell 2x fp32 path) -----------------
__device__ __forceinline__ u64 pack2(float lo, float hi) {
    u64 r; asm("mov.b64 %0, {%1,%2};" : "=l"(r) : "f"(lo), "f"(hi)); return r;
}
__device__ __forceinline__ u64 dup2(float v) {
    u64 r; asm("mov.b64 %0, {%1,%1};" : "=l"(r) : "f"(v)); return r;
}
__device__ __forceinline__ float2 unpack2(u64 v) {
    float2 f; asm("mov.b64 {%0,%1}, %2;" : "=f"(f.x), "=f"(f.y) : "l"(v)); return f;
}
__device__ __forceinline__ u64 fma2(u64 a, u64 b, u64 c) {
    u64 d; asm("fma.rn.f32x2 %0,%1,%2,%3;" : "=l"(d) : "l"(a), "l"(b), "l"(c)); return d;
}
__device__ __forceinline__ u64 mul2(u64 a, u64 b) {
    u64 d; asm("mul.rn.f32x2 %0,%1,%2;" : "=l"(d) : "l"(a), "l"(b)); return d;
}
__device__ __forceinline__ u64 add2(u64 a, u64 b) {
    u64 d; asm("add.rn.f32x2 %0,%1,%2;" : "=l"(d) : "l"(a), "l"(b)); return d;
}
__device__ __forceinline__ float rcpa(float x) {
    float r; asm("rcp.approx.f32 %0,%1;" : "=f"(r) : "f"(x)); return r;
}

// gelu(x) = relu(x) - 0.5|x| / poly4(|x|)^4 ; poly coeffs pre-folded with 1/sqrt2
// (A&S 7.1.27, |eps|<=5e-4)
__device__ __forceinline__ float gelu_fast(float x) {
    float ax = fabsf(x);
    float p  = fmaf(0.019527f, ax, 0.00034366f);
    p = fmaf(p, ax, 0.1151945f);
    p = fmaf(p, ax, 0.1968561f);
    p = fmaf(p, ax, 1.0f);
    float p2 = p * p;
    float r  = rcpa(p2 * p2);
    float hax = 0.5f * ax;
    float t1  = fmaf(0.5f, x, hax);     // relu(x)
    return fmaf(-hax, r, t1);
}

// ---------------- weight-prep: Wcat[l] = [Wq*scale | Wk | Wtop+Wbot | Wbot] ------
__global__ void prep_wcat(const float* __restrict__ Wq, const float* __restrict__ Wk,
                          const float* __restrict__ Wv1, float* __restrict__ Wcat,
                          float scale)
{
    int l   = blockIdx.y;
    int idx = blockIdx.x * 256 + threadIdx.x;      // 0..65535
    int row = idx >> 9;                             // 0..127
    int col = idx & 511;
    int c   = col & 127;
    const float* Wq_l  = Wq  + (size_t)l * ND * ND;
    const float* Wk_l  = Wk  + (size_t)l * ND * ND;
    const float* Wtop  = Wv1 + (size_t)l * 2 * ND * ND;
    const float* Wbot  = Wtop + (size_t)ND * ND;
    float v;
    switch (col >> 7) {
        case 0:  v = Wq_l[row * ND + c] * scale;                  break;
        case 1:  v = Wk_l[row * ND + c];                          break;
        case 2:  v = Wtop[row * ND + c] + Wbot[row * ND + c];     break;
        default: v = Wbot[row * ND + c];                          break;
    }
    Wcat[(size_t)l * ND * NCAT + idx] = v;
}

// ---------------- qkpq GEMM: C[8192,512] = A[8192,128] @ W[128,512] --------------
__global__ __launch_bounds__(256) void gemm_qkpq(const float* __restrict__ A,
                                                 const float* __restrict__ W,
                                                 float* __restrict__ C)
{
    __shared__ float As[2][16 * 64];
    __shared__ float Bs[2][16 * 128];
    const int t    = threadIdx.x;
    const int bm   = blockIdx.x * 64;
    const int bn   = blockIdx.y * 128;
    const int ty   = t >> 5;
    const int lane = t & 31;

    const int am  = t >> 2;
    const int ak4 = (t & 3) << 2;
    const int bk  = t >> 5;
    const int bn4 = (t & 31) << 2;

    u64 acc2[4][4];
#pragma unroll
    for (int i = 0; i < 4; i++)
#pragma unroll
        for (int j = 0; j < 4; j++) acc2[i][j] = 0;

    {
        float4 av = *(const float4*)(A + (size_t)(bm + am) * ND + ak4);
        As[0][(ak4 + 0) * 64 + am] = av.x;
        As[0][(ak4 + 1) * 64 + am] = av.y;
        As[0][(ak4 + 2) * 64 + am] = av.z;
        As[0][(ak4 + 3) * 64 + am] = av.w;
        *(float4*)&Bs[0][bk * 128 + bn4]       = *(const float4*)(W + (size_t)bk * NCAT + bn + bn4);
        *(float4*)&Bs[0][(bk + 8) * 128 + bn4] = *(const float4*)(W + (size_t)(bk + 8) * NCAT + bn + bn4);
    }
    __syncthreads();

    for (int c = 0; c < 8; c++) {
        const int cb = c & 1;
        float4 pa, pb0, pb1;
        if (c < 7) {
            int k0n = (c + 1) * 16;
            pa  = *(const float4*)(A + (size_t)(bm + am) * ND + k0n + ak4);
            pb0 = *(const float4*)(W + (size_t)(k0n + bk) * NCAT + bn + bn4);
            pb1 = *(const float4*)(W + (size_t)(k0n + bk + 8) * NCAT + bn + bn4);
        }
        const float* Ab = As[cb];
        const float* Bb = Bs[cb];
#pragma unroll
        for (int kk = 0; kk < 16; kk++) {
            double2 ad0 = *(const double2*)&Ab[kk * 64 + ty * 8];
            double2 ad1 = *(const double2*)&Ab[kk * 64 + ty * 8 + 4];
            u64 a01 = __double_as_longlong(ad0.x);
            u64 a23 = __double_as_longlong(ad0.y);
            u64 a45 = __double_as_longlong(ad1.x);
            u64 a67 = __double_as_longlong(ad1.y);
            float4 b4 = *(const float4*)&Bb[kk * 128 + lane * 4];
            u64 b0 = dup2(b4.x), b1 = dup2(b4.y), b2 = dup2(b4.z), b3 = dup2(b4.w);
            acc2[0][0] = fma2(a01, b0, acc2[0][0]); acc2[0][1] = fma2(a01, b1, acc2[0][1]);
            acc2[0][2] = fma2(a01, b2, acc2[0][2]); acc2[0][3] = fma2(a01, b3, acc2[0][3]);
            acc2[1][0] = fma2(a23, b0, acc2[1][0]); acc2[1][1] = fma2(a23, b1, acc2[1][1]);
            acc2[1][2] = fma2(a23, b2, acc2[1][2]); acc2[1][3] = fma2(a23, b3, acc2[1][3]);
            acc2[2][0] = fma2(a45, b0, acc2[2][0]); acc2[2][1] = fma2(a45, b1, acc2[2][1]);
            acc2[2][2] = fma2(a45, b2, acc2[2][2]); acc2[2][3] = fma2(a45, b3, acc2[2][3]);
            acc2[3][0] = fma2(a67, b0, acc2[3][0]); acc2[3][1] = fma2(a67, b1, acc2[3][1]);
            acc2[3][2] = fma2(a67, b2, acc2[3][2]); acc2[3][3] = fma2(a67, b3, acc2[3][3]);
        }
        __syncthreads();
        if (c < 7) {
            const int nb = cb ^ 1;
            As[nb][(ak4 + 0) * 64 + am] = pa.x;
            As[nb][(ak4 + 1) * 64 + am] = pa.y;
            As[nb][(ak4 + 2) * 64 + am] = pa.z;
            As[nb][(ak4 + 3) * 64 + am] = pa.w;
            *(float4*)&Bs[nb][bk * 128 + bn4]       = pb0;
            *(float4*)&Bs[nb][(bk + 8) * 128 + bn4] = pb1;
            __syncthreads();
        }
    }

#pragma unroll
    for (int p = 0; p < 4; p++) {
        float2 r0 = unpack2(acc2[p][0]);
        float2 r1 = unpack2(acc2[p][1]);
        float2 r2 = unpack2(acc2[p][2]);
        float2 r3 = unpack2(acc2[p][3]);
        float4 oA; oA.x = r0.x; oA.y = r1.x; oA.z = r2.x; oA.w = r3.x;
        float4 oB; oB.x = r0.y; oB.y = r1.y; oB.z = r2.y; oB.w = r3.y;
        *(float4*)(C + (size_t)(bm + ty * 8 + 2 * p)     * NCAT + bn + lane * 4) = oA;
        *(float4*)(C + (size_t)(bm + ty * 8 + 2 * p + 1) * NCAT + bn + lane * 4) = oB;
    }
}

// ---------------- fused attention + weighted-gelu-sum: 2 CTAs per batch ---------
__global__ void attn_u_kernel(const float* __restrict__ qkpq,
                              const float* __restrict__ bv1, float* __restrict__ u)
{
    extern __shared__ float sm[];
    float* sq = sm;                   // 32 rows
    float* sk = sq + 32 * SPITCH;     // 64 rows
    float* sP = sk + 64 * SPITCH;     // 32 rows (P + bv1)
    float* sQ = sP + 32 * SPITCH;     // 64 rows (negated)
    float* sa = sQ + 64 * SPITCH;     // 32*64 logits/attn

    const int t  = threadIdx.x;       // 512 threads
    const int b  = blockIdx.x >> 1;
    const int r0 = (blockIdx.x & 1) * 32;
    const size_t base = (size_t)b * NKE;

    {
        for (int idx = t; idx < 32 * ND / 4; idx += 512) {
            int row = idx >> 5;
            int col = (idx & 31) << 2;
            const float* src = qkpq + (base + r0 + row) * NCAT + col;
            *(float4*)&sq[row * SPITCH + col] = *(const float4*)(src);            // q
            float4 pv = *(const float4*)(src + 2 * ND);                           // P
            float4 bv = *(const float4*)(bv1 + col);
            pv.x += bv.x; pv.y += bv.y; pv.z += bv.z; pv.w += bv.w;
            *(float4*)&sP[row * SPITCH + col] = pv;
        }
        for (int idx = t; idx < 64 * ND / 4; idx += 512) {
            int row = idx >> 5;
            int col = (idx & 31) << 2;
            const float* src = qkpq + (base + row) * NCAT + col;
            *(float4*)&sk[row * SPITCH + col] = *(const float4*)(src + ND);       // k
            float4 qv = *(const float4*)(src + 3 * ND);                           // Q
            qv.x = -qv.x; qv.y = -qv.y; qv.z = -qv.z; qv.w = -qv.w;
            *(float4*)&sQ[row * SPITCH + col] = qv;
        }
    }
    __syncthreads();

    // logits — packed pairwise dot products
    {
        const int i  = t >> 4;
        const int jb = t & 15;
        u64 acc2[4] = {0, 0, 0, 0};
        const float* qrow = sq + i * SPITCH;
        for (int d = 0; d < ND; d += 4) {
            double2 qd = *(const double2*)(qrow + d);
            u64 q01 = __double_as_longlong(qd.x);
            u64 q23 = __double_as_longlong(qd.y);
#pragma unroll
            for (int jj = 0; jj < 4; jj++) {
                double2 kd = *(const double2*)(sk + (jb + jj * 16) * SPITCH + d);
                acc2[jj] = fma2(q01, __double_as_longlong(kd.x), acc2[jj]);
                acc2[jj] = fma2(q23, __double_as_longlong(kd.y), acc2[jj]);
            }
        }
#pragma unroll
        for (int jj = 0; jj < 4; jj++) {
            float2 f = unpack2(acc2[jj]);
            sa[i * 64 + jb + jj * 16] = f.x + f.y;
        }
    }
    __syncthreads();

    // softmax
    {
        const int w = t >> 5, lane = t & 31;
#pragma unroll
        for (int r = 0; r < 2; r++) {
            int i = w * 2 + r;
            float v0 = sa[i * 64 + lane], v1 = sa[i * 64 + lane + 32];
            float mx = fmaxf(v0, v1);
            for (int o = 16; o; o >>= 1) mx = fmaxf(mx, __shfl_xor_sync(0xffffffffu, mx, o));
            float e0 = __expf(v0 - mx), e1 = __expf(v1 - mx);
            float s = e0 + e1;
            for (int o = 16; o; o >>= 1) s += __shfl_xor_sync(0xffffffffu, s, o);
            float inv = 1.0f / s;
            sa[i * 64 + lane] = e0 * inv;
            sa[i * 64 + lane + 32] = e1 * inv;
        }
    }
    __syncthreads();

    // u accumulate — packed f32x2 gelu chain (folded coeffs, xor-negation)
    {
        const int w = t >> 5, lane = t & 31;
        const int dl = lane << 2;

        const u64 B4   = pack2(0.019527f, 0.019527f);
        const u64 B3   = pack2(0.00034366f, 0.00034366f);
        const u64 B2   = pack2(0.1151945f, 0.1151945f);
        const u64 B1   = pack2(0.1968561f, 0.1968561f);
        const u64 ONE  = pack2(1.0f, 1.0f);
        const u64 HALF = pack2(0.5f, 0.5f);
        const u64 ABSM = 0x7FFFFFFF7FFFFFFFULL;
        const u64 SGN  = 0x8000000080000000ULL;

#pragma unroll
        for (int ii = 0; ii < 2; ii++) {
            int i = w + ii * 16;
            const double2 Pd = *(const double2*)(sP + i * SPITCH + dl);
            const u64 P01 = __double_as_longlong(Pd.x);
            const u64 P23 = __double_as_longlong(Pd.y);
            u64 acc01 = 0, acc23 = 0;
            for (int j = 0; j < NKE; j += 4) {
                float4 att = *(const float4*)&sa[i * 64 + j];
#pragma unroll
                for (int jj = 0; jj < 4; jj++) {
                    float aw = (jj == 0) ? att.x : (jj == 1) ? att.y : (jj == 2) ? att.z : att.w;
                    const u64 AW = dup2(aw);
                    const double2 Qd = *(const double2*)(sQ + (j + jj) * SPITCH + dl);
                    u64 x01 = add2(P01, __double_as_longlong(Qd.x));
                    u64 x23 = add2(P23, __double_as_longlong(Qd.y));
                    {
                        u64 ax = x01 & ABSM;
                        u64 p  = fma2(B4, ax, B3);
                        p = fma2(p, ax, B2);
                        p = fma2(p, ax, B1);
                        p = fma2(p, ax, ONE);
                        u64 p2 = mul2(p, p);
                        u64 p4 = mul2(p2, p2);
                        float2 pf = unpack2(p4);
                        u64 r   = pack2(rcpa(pf.x), rcpa(pf.y));
                        u64 hax = mul2(ax, HALF);
                        u64 t1  = fma2(x01, HALF, hax);      // relu(x)
                        u64 nh  = hax ^ SGN;                 // -0.5|x| (alu pipe)
                        u64 g   = fma2(nh, r, t1);
                        acc01 = fma2(AW, g, acc01);
                    }
                    {
                        u64 ax = x23 & ABSM;
                        u64 p  = fma2(B4, ax, B3);
                        p = fma2(p, ax, B2);
                        p = fma2(p, ax, B1);
                        p = fma2(p, ax, ONE);
                        u64 p2 = mul2(p, p);
                        u64 p4 = mul2(p2, p2);
                        float2 pf = unpack2(p4);
                        u64 r   = pack2(rcpa(pf.x), rcpa(pf.y));
                        u64 hax = mul2(ax, HALF);
                        u64 t1  = fma2(x23, HALF, hax);
                        u64 nh  = hax ^ SGN;
                        u64 g   = fma2(nh, r, t1);
                        acc23 = fma2(AW, g, acc23);
                    }
                }
            }
            float2 lo = unpack2(acc01);
            float2 hi = unpack2(acc23);
            float4 o; o.x = lo.x; o.y = lo.y; o.z = hi.x; o.w = hi.y;
            *(float4*)(u + (base + r0 + i) * ND + dl) = o;
        }
    }
}

// ---------------- persistent weights-resident fused MLP (512 thr, 4x2) ----------
// Grid 148, 512 threads (16 warps/SM). Microtile 4 rows x 2 cols keeps crossbar
// traffic ~flat vs 256-thr 4x4 while doubling issue-side warps.
__device__ __forceinline__ void gemm_res(const float* __restrict__ Wb,
                                         const float* __restrict__ uT,
                                         int g, int h, int lane, u64 acc2[2][2])
{
    const float* ap = uT + g * 4;
    const float* bp = Wb + h * 64 + lane * 2;

    double2 a0 = *(const double2*)(ap);
    float2  c0 = *(const float2*)(bp);
    double2 a1 = *(const double2*)(ap + UTP);
    float2  c1 = *(const float2*)(bp + 128);

#pragma unroll 8
    for (int kk = 0; kk < 128; kk += 2) {
        const int nk = (kk + 2 < 128) ? kk + 2 : 0;  // clamp; values unused last iter
        double2 an0 = *(const double2*)(ap + nk * UTP);
        float2  cn0 = *(const float2*)(bp + nk * 128);
        double2 an1 = *(const double2*)(ap + (nk + 1) * UTP);
        float2  cn1 = *(const float2*)(bp + (nk + 1) * 128);
        {
            u64 a01 = __double_as_longlong(a0.x);
            u64 a23 = __double_as_longlong(a0.y);
            u64 b0 = dup2(c0.x), b1 = dup2(c0.y);
            acc2[0][0] = fma2(a01, b0, acc2[0][0]);
            acc2[0][1] = fma2(a01, b1, acc2[0][1]);
            acc2[1][0] = fma2(a23, b0, acc2[1][0]);
            acc2[1][1] = fma2(a23, b1, acc2[1][1]);
        }
        {
            u64 a01 = __double_as_longlong(a1.x);
            u64 a23 = __double_as_longlong(a1.y);
            u64 b0 = dup2(c1.x), b1 = dup2(c1.y);
            acc2[0][0] = fma2(a01, b0, acc2[0][0]);
            acc2[0][1] = fma2(a01, b1, acc2[0][1]);
            acc2[1][0] = fma2(a23, b0, acc2[1][0]);
            acc2[1][1] = fma2(a23, b1, acc2[1][1]);
        }
        a0 = an0; c0 = cn0; a1 = an1; c1 = cn1;
    }
}

__global__ __launch_bounds__(512) void fused_mlp(
    const float* __restrict__ u,   const float* __restrict__ xa,
    const float* __restrict__ Wv2, const float* __restrict__ bv2,
    const float* __restrict__ lng, const float* __restrict__ lnb,
    const float* __restrict__ Wm1, const float* __restrict__ bm1,
    const float* __restrict__ Wm2, const float* __restrict__ bm2,
    float* __restrict__ xo)
{
    extern __shared__ float sm[];
    float* Wall = sm;                 // 3 * 16384 = 49152
    float* uT   = Wall + 3 * 16384;   // 128 * 36  = 4608
    float* hs   = uT + 128 * UTP;     // 32 * 128  = 4096   total 57856 f = 226KB

    const int t    = threadIdx.x;     // 512
    const int wid  = t >> 5;          // 0..15
    const int lane = t & 31;
    const int g    = wid >> 1;        // row group 0..7 -> rows g*4..+3
    const int h    = wid & 1;         // column half
    const int cb   = h * 64 + lane * 2;   // this thread's 2 cols
    const int cl   = lane << 2;           // LN-pass cols (float4)

    // ---- load all three weights once
    {
        const float* srcs[3] = {Wv2, Wm1, Wm2};
#pragma unroll
        for (int w = 0; w < 3; w++) {
            float4* dst = (float4*)(Wall + w * 16384);
            const float4* src = (const float4*)srcs[w];
            for (int i = t; i < 4096; i += 512) dst[i] = src[i];
        }
    }
    __syncthreads();

    float4 gg = *(const float4*)(lng + cl);
    float4 lb = *(const float4*)(lnb + cl);
    float2 b1v = *(const float2*)(bv2 + cb);
    float2 b2v = *(const float2*)(bm1 + cb);
    float2 b3v = *(const float2*)(bm2 + cb);

    for (int tile = blockIdx.x; tile < NTILES; tile += PGRID) {
        const int r0 = tile * 32;

        // stage u transposed
        for (int idx = t; idx < 32 * ND; idx += 512) {
            int r = idx >> 7, k = idx & 127;
            uT[k * UTP + r] = u[(size_t)(r0 + r) * ND + k];
        }
        __syncthreads();

        u64 acc2[2][2];

        // ---- GEMM1: h2 = u@Wv2 + bv2 + x -> hs (raw)
        acc2[0][0] = acc2[0][1] = acc2[1][0] = acc2[1][1] = 0;
        gemm_res(Wall, uT, g, h, lane, acc2);
        {
#pragma unroll
            for (int p = 0; p < 2; p++) {
                float2 f0 = unpack2(acc2[p][0]);   // col cb,   rows (lo,hi)
                float2 f1 = unpack2(acc2[p][1]);   // col cb+1
                int rlo = g * 4 + 2 * p, rhi = rlo + 1;
                float2 xlo = *(const float2*)(xa + (size_t)(r0 + rlo) * ND + cb);
                float2 xhi = *(const float2*)(xa + (size_t)(r0 + rhi) * ND + cb);
                float2 olo, ohi;
                olo.x = f0.x + b1v.x + xlo.x;  olo.y = f1.x + b1v.y + xlo.y;
                ohi.x = f0.y + b1v.x + xhi.x;  ohi.y = f1.y + b1v.y + xhi.y;
                *(float2*)&hs[rlo * 128 + cb] = olo;
                *(float2*)&hs[rhi * 128 + cb] = ohi;
            }
        }
        __syncthreads();

        // ---- LayerNorm in place on hs (warp wid handles rows wid*2, wid*2+1)
        {
#pragma unroll
            for (int i = 0; i < 2; i++) {
                int r = wid * 2 + i;
                float4 v = *(const float4*)&hs[r * 128 + cl];
                float s  = v.x + v.y + v.z + v.w;
                float s2 = v.x * v.x + v.y * v.y + v.z * v.z + v.w * v.w;
                for (int o = 16; o; o >>= 1) {
                    s  += __shfl_xor_sync(0xffffffffu, s, o);
                    s2 += __shfl_xor_sync(0xffffffffu, s2, o);
                }
                float mu  = s * (1.0f / ND);
                float var = s2 * (1.0f / ND) - mu * mu;
                float inv = rsqrtf(var + 1e-5f);
                float4 o4;
                o4.x = (v.x - mu) * inv * gg.x + lb.x;
                o4.y = (v.y - mu) * inv * gg.y + lb.y;
                o4.z = (v.z - mu) * inv * gg.z + lb.z;
                o4.w = (v.w - mu) * inv * gg.w + lb.w;
                *(float4*)&hs[r * 128 + cl] = o4;
            }
        }
        __syncthreads();
        for (int idx = t; idx < 32 * ND; idx += 512) {
            int r = idx >> 7, k = idx & 127;
            uT[k * UTP + r] = hs[r * 128 + k];
        }
        __syncthreads();

        // ---- GEMM2: t = gelu(ln@Wm1 + bm1) -> hs
        acc2[0][0] = acc2[0][1] = acc2[1][0] = acc2[1][1] = 0;
        gemm_res(Wall + 16384, uT, g, h, lane, acc2);
        {
#pragma unroll
            for (int p = 0; p < 2; p++) {
                float2 f0 = unpack2(acc2[p][0]);
                float2 f1 = unpack2(acc2[p][1]);
                int rlo = g * 4 + 2 * p, rhi = rlo + 1;
                float2 olo, ohi;
                olo.x = gelu_fast(f0.x + b2v.x);  olo.y = gelu_fast(f1.x + b2v.y);
                ohi.x = gelu_fast(f0.y + b2v.x);  ohi.y = gelu_fast(f1.y + b2v.y);
                *(float2*)&hs[rlo * 128 + cb] = olo;
                *(float2*)&hs[rhi * 128 + cb] = ohi;
            }
        }
        __syncthreads();
        for (int idx = t; idx < 32 * ND; idx += 512) {
            int r = idx >> 7, k = idx & 127;
            uT[k * UTP + r] = hs[r * 128 + k];
        }
        __syncthreads();

        // ---- GEMM3: out = x + t@Wm2 + bm2 -> global
        acc2[0][0] = acc2[0][1] = acc2[1][0] = acc2[1][1] = 0;
        gemm_res(Wall + 32768, uT, g, h, lane, acc2);
        {
#pragma unroll
            for (int p = 0; p < 2; p++) {
                float2 f0 = unpack2(acc2[p][0]);
                float2 f1 = unpack2(acc2[p][1]);
                int rlo = g * 4 + 2 * p, rhi = rlo + 1;
                float2 xlo = *(const float2*)(xa + (size_t)(r0 + rlo) * ND + cb);
                float2 xhi = *(const float2*)(xa + (size_t)(r0 + rhi) * ND + cb);
                float2 olo, ohi;
                olo.x = f0.x + b3v.x + xlo.x;  olo.y = f1.x + b3v.y + xlo.y;
                ohi.x = f0.y + b3v.x + xhi.x;  ohi.y = f1.y + b3v.y + xhi.y;
                *(float2*)(xo + (size_t)(r0 + rlo) * ND + cb) = olo;
                *(float2*)(xo + (size_t)(r0 + rhi) * ND + cb) = ohi;
            }
        }
        __syncthreads();   // protect uT before next tile restages
    }
}

// ---------------- fused head: pool + proj(gelu) + mu/sp projections -------------
__global__ void head_kernel(const float* __restrict__ x,
                            const float* __restrict__ Wp,  const float* __restrict__ bp,
                            const float* __restrict__ Wmu, const float* __restrict__ bmu,
                            const float* __restrict__ Wsp, const float* __restrict__ bsp,
                            float* __restrict__ out)
{
    __shared__ float spool[ND];
    __shared__ float sproj[NS];
    const int b = blockIdx.x;
    const int t = threadIdx.x;   // 128 threads

    {
        float s = 0.f;
        const float* p = x + (size_t)b * NKE * ND + t;
        for (int i = 0; i < NKE; i++) s += p[i * ND];
        spool[t] = s;
    }
    __syncthreads();
    {
        float acc = bp[t];
        for (int d = 0; d < ND; d++) acc += spool[d] * Wp[d * NS + t];
        sproj[t] = gelu_fast(acc);
    }
    __syncthreads();
    {
        float amu = bmu[t], asp = bsp[t];
        for (int s = 0; s < NS; s++) {
            float f = sproj[s];
            amu += f * Wmu[s * NS + t];
            asp += f * Wsp[s * NS + t];
        }
        out[(size_t)b * NS + t] = amu;
        out[(size_t)NB * NS + (size_t)b * NS + t] = asp;
    }
}

// ---------------- launch --------------------------------------------------------
extern "C" void kernel_launch(void* const* d_in, const int* in_sizes, int n_in,
                              void* d_out, int out_size)
{
    const float* x_in = (const float*)d_in[0];
    const float* Wk   = (const float*)d_in[1];
    const float* Wq   = (const float*)d_in[2];
    const float* Wv1  = (const float*)d_in[3];
    const float* bv1  = (const float*)d_in[4];
    const float* Wv2  = (const float*)d_in[5];
    const float* bv2  = (const float*)d_in[6];
    const float* lng  = (const float*)d_in[7];
    const float* lnb  = (const float*)d_in[8];
    const float* Wm1  = (const float*)d_in[9];
    const float* bm1  = (const float*)d_in[10];
    const float* Wm2  = (const float*)d_in[11];
    const float* bm2  = (const float*)d_in[12];
    const float* Wp   = (const float*)d_in[13];
    const float* bp   = (const float*)d_in[14];
    const float* Wmu  = (const float*)d_in[15];
    const float* bmu  = (const float*)d_in[16];
    const float* Wsp  = (const float*)d_in[17];
    const float* bsp  = (const float*)d_in[18];
    float* out = (float*)d_out;

    float *px, *pqkpq, *pu, *pwcat;
    cudaGetSymbolAddress((void**)&px,    g_x);
    cudaGetSymbolAddress((void**)&pqkpq, g_qkpq);
    cudaGetSymbolAddress((void**)&pu,    g_u);
    cudaGetSymbolAddress((void**)&pwcat, g_wcat);

    const int SMEM_AU = (192 * SPITCH + 32 * NKE) * (int)sizeof(float);   // ~107KB
    cudaFuncSetAttribute(attn_u_kernel, cudaFuncAttributeMaxDynamicSharedMemorySize, SMEM_AU);
    const int SMEM_P = (3 * 16384 + 128 * UTP + 32 * 128) * (int)sizeof(float);  // 226KB
    cudaFuncSetAttribute(fused_mlp, cudaFuncAttributeMaxDynamicSharedMemorySize, SMEM_P);

    const float scale = 1.0f / sqrtf((float)ND);

    prep_wcat<<<dim3(256, NL), 256>>>(Wq, Wk, Wv1, pwcat, scale);

    dim3 gq(MROWS / 64, NCAT / 128);    // (128, 4) = 512 CTAs
    for (int l = 0; l < NL; l++) {
        const float* Wcat_l = pwcat + (size_t)l * ND * NCAT;
        const float* bv1_l = bv1 + (size_t)l * ND;
        const float* Wv2_l = Wv2 + (size_t)l * ND * ND;
        const float* bv2_l = bv2 + (size_t)l * ND;
        const float* g_l   = lng + (size_t)l * ND;
        const float* b_l   = lnb + (size_t)l * ND;
        const float* Wm1_l = Wm1 + (size_t)l * ND * ND;
        const float* bm1_l = bm1 + (size_t)l * ND;
        const float* Wm2_l = Wm2 + (size_t)l * ND * ND;
        const float* bm2_l = bm2 + (size_t)l * ND;

        const float* xa = (l == 0) ? x_in : px;

        gemm_qkpq<<<gq, 256>>>(xa, Wcat_l, pqkpq);
        attn_u_kernel<<<NB * 2, 512, SMEM_AU>>>(pqkpq, bv1_l, pu);
        fused_mlp<<<PGRID, 512, SMEM_P>>>(pu, xa, Wv2_l, bv2_l, g_l, b_l,
                                          Wm1_l, bm1_l, Wm2_l, bm2_l, px);
    }

    head_kernel<<<NB, ND>>>(px, Wp, bp, Wmu, bmu, Wsp, bsp, out);
}

// round 15
// speedup vs baseline: 1.0421x; 1.0421x over previous
#include <cuda_runtime.h>
#include <cmath>

#define NB 128   // batch
#define NKE 64   // entities (K)
#define ND 128   // feature dim D
#define NS 128   // S
#define NL 2     // layers
#define MROWS (NB*NKE)   // 8192
#define SPITCH 132       // padded smem row stride (floats) for attn tiles
#define NCAT 512         // fused q|k|P|Q width
#define UTP 36           // transposed-tile row stride (floats), 32+4, mult of 4
#define NTILES (MROWS/32) // 256
#define PGRID 148        // persistent grid for fused_mlp

typedef unsigned long long u64;

// ---------------- scratch (static device arrays; no allocation) ----------------
__device__ float g_x[MROWS*ND];
__device__ float g_qkpq[MROWS*NCAT];          // 16 MB
__device__ float g_u[MROWS*ND];
__device__ float g_wcat[NL*ND*NCAT];          // per-layer fused weights

// ---------------- f32x2 packed helpers (Blackwell 2x fp32 path) -----------------
__device__ __forceinline__ u64 pack2(float lo, float hi) {
    u64 r; asm("mov.b64 %0, {%1,%2};" : "=l"(r) : "f"(lo), "f"(hi)); return r;
}
__device__ __forceinline__ u64 dup2(float v) {
    u64 r; asm("mov.b64 %0, {%1,%1};" : "=l"(r) : "f"(v)); return r;
}
__device__ __forceinline__ float2 unpack2(u64 v) {
    float2 f; asm("mov.b64 {%0,%1}, %2;" : "=f"(f.x), "=f"(f.y) : "l"(v)); return f;
}
__device__ __forceinline__ u64 fma2(u64 a, u64 b, u64 c) {
    u64 d; asm("fma.rn.f32x2 %0,%1,%2,%3;" : "=l"(d) : "l"(a), "l"(b), "l"(c)); return d;
}
__device__ __forceinline__ u64 mul2(u64 a, u64 b) {
    u64 d; asm("mul.rn.f32x2 %0,%1,%2;" : "=l"(d) : "l"(a), "l"(b)); return d;
}
__device__ __forceinline__ u64 add2(u64 a, u64 b) {
    u64 d; asm("add.rn.f32x2 %0,%1,%2;" : "=l"(d) : "l"(a), "l"(b)); return d;
}
__device__ __forceinline__ float rcpa(float x) {
    float r; asm("rcp.approx.f32 %0,%1;" : "=f"(r) : "f"(x)); return r;
}

// gelu(x) = relu(x) - 0.5|x| / poly4(|x|)^4 ; poly coeffs pre-folded with 1/sqrt2
// (A&S 7.1.27, |eps|<=5e-4)
__device__ __forceinline__ float gelu_fast(float x) {
    float ax = fabsf(x);
    float p  = fmaf(0.019527f, ax, 0.00034366f);
    p = fmaf(p, ax, 0.1151945f);
    p = fmaf(p, ax, 0.1968561f);
    p = fmaf(p, ax, 1.0f);
    float p2 = p * p;
    float r  = rcpa(p2 * p2);
    float hax = 0.5f * ax;
    float t1  = fmaf(0.5f, x, hax);     // relu(x)
    return fmaf(-hax, r, t1);
}

// ---------------- weight-prep: Wcat[l] = [Wq*scale | Wk | Wtop+Wbot | Wbot] ------
__global__ void prep_wcat(const float* __restrict__ Wq, const float* __restrict__ Wk,
                          const float* __restrict__ Wv1, float* __restrict__ Wcat,
                          float scale)
{
    int l   = blockIdx.y;
    int idx = blockIdx.x * 256 + threadIdx.x;      // 0..65535
    int row = idx >> 9;                             // 0..127
    int col = idx & 511;
    int c   = col & 127;
    const float* Wq_l  = Wq  + (size_t)l * ND * ND;
    const float* Wk_l  = Wk  + (size_t)l * ND * ND;
    const float* Wtop  = Wv1 + (size_t)l * 2 * ND * ND;
    const float* Wbot  = Wtop + (size_t)ND * ND;
    float v;
    switch (col >> 7) {
        case 0:  v = Wq_l[row * ND + c] * scale;                  break;
        case 1:  v = Wk_l[row * ND + c];                          break;
        case 2:  v = Wtop[row * ND + c] + Wbot[row * ND + c];     break;
        default: v = Wbot[row * ND + c];                          break;
    }
    Wcat[(size_t)l * ND * NCAT + idx] = v;
}

// ---------------- qkpq GEMM: C[8192,512] = A[8192,128] @ W[128,512] --------------
__global__ __launch_bounds__(256) void gemm_qkpq(const float* __restrict__ A,
                                                 const float* __restrict__ W,
                                                 float* __restrict__ C)
{
    __shared__ float As[2][16 * 64];
    __shared__ float Bs[2][16 * 128];
    const int t    = threadIdx.x;
    const int bm   = blockIdx.x * 64;
    const int bn   = blockIdx.y * 128;
    const int ty   = t >> 5;
    const int lane = t & 31;

    const int am  = t >> 2;
    const int ak4 = (t & 3) << 2;
    const int bk  = t >> 5;
    const int bn4 = (t & 31) << 2;

    u64 acc2[4][4];
#pragma unroll
    for (int i = 0; i < 4; i++)
#pragma unroll
        for (int j = 0; j < 4; j++) acc2[i][j] = 0;

    {
        float4 av = *(const float4*)(A + (size_t)(bm + am) * ND + ak4);
        As[0][(ak4 + 0) * 64 + am] = av.x;
        As[0][(ak4 + 1) * 64 + am] = av.y;
        As[0][(ak4 + 2) * 64 + am] = av.z;
        As[0][(ak4 + 3) * 64 + am] = av.w;
        *(float4*)&Bs[0][bk * 128 + bn4]       = *(const float4*)(W + (size_t)bk * NCAT + bn + bn4);
        *(float4*)&Bs[0][(bk + 8) * 128 + bn4] = *(const float4*)(W + (size_t)(bk + 8) * NCAT + bn + bn4);
    }
    __syncthreads();

    for (int c = 0; c < 8; c++) {
        const int cb = c & 1;
        float4 pa, pb0, pb1;
        if (c < 7) {
            int k0n = (c + 1) * 16;
            pa  = *(const float4*)(A + (size_t)(bm + am) * ND + k0n + ak4);
            pb0 = *(const float4*)(W + (size_t)(k0n + bk) * NCAT + bn + bn4);
            pb1 = *(const float4*)(W + (size_t)(k0n + bk + 8) * NCAT + bn + bn4);
        }
        const float* Ab = As[cb];
        const float* Bb = Bs[cb];
#pragma unroll
        for (int kk = 0; kk < 16; kk++) {
            double2 ad0 = *(const double2*)&Ab[kk * 64 + ty * 8];
            double2 ad1 = *(const double2*)&Ab[kk * 64 + ty * 8 + 4];
            u64 a01 = __double_as_longlong(ad0.x);
            u64 a23 = __double_as_longlong(ad0.y);
            u64 a45 = __double_as_longlong(ad1.x);
            u64 a67 = __double_as_longlong(ad1.y);
            float4 b4 = *(const float4*)&Bb[kk * 128 + lane * 4];
            u64 b0 = dup2(b4.x), b1 = dup2(b4.y), b2 = dup2(b4.z), b3 = dup2(b4.w);
            acc2[0][0] = fma2(a01, b0, acc2[0][0]); acc2[0][1] = fma2(a01, b1, acc2[0][1]);
            acc2[0][2] = fma2(a01, b2, acc2[0][2]); acc2[0][3] = fma2(a01, b3, acc2[0][3]);
            acc2[1][0] = fma2(a23, b0, acc2[1][0]); acc2[1][1] = fma2(a23, b1, acc2[1][1]);
            acc2[1][2] = fma2(a23, b2, acc2[1][2]); acc2[1][3] = fma2(a23, b3, acc2[1][3]);
            acc2[2][0] = fma2(a45, b0, acc2[2][0]); acc2[2][1] = fma2(a45, b1, acc2[2][1]);
            acc2[2][2] = fma2(a45, b2, acc2[2][2]); acc2[2][3] = fma2(a45, b3, acc2[2][3]);
            acc2[3][0] = fma2(a67, b0, acc2[3][0]); acc2[3][1] = fma2(a67, b1, acc2[3][1]);
            acc2[3][2] = fma2(a67, b2, acc2[3][2]); acc2[3][3] = fma2(a67, b3, acc2[3][3]);
        }
        __syncthreads();
        if (c < 7) {
            const int nb = cb ^ 1;
            As[nb][(ak4 + 0) * 64 + am] = pa.x;
            As[nb][(ak4 + 1) * 64 + am] = pa.y;
            As[nb][(ak4 + 2) * 64 + am] = pa.z;
            As[nb][(ak4 + 3) * 64 + am] = pa.w;
            *(float4*)&Bs[nb][bk * 128 + bn4]       = pb0;
            *(float4*)&Bs[nb][(bk + 8) * 128 + bn4] = pb1;
            __syncthreads();
        }
    }

#pragma unroll
    for (int p = 0; p < 4; p++) {
        float2 r0 = unpack2(acc2[p][0]);
        float2 r1 = unpack2(acc2[p][1]);
        float2 r2 = unpack2(acc2[p][2]);
        float2 r3 = unpack2(acc2[p][3]);
        float4 oA; oA.x = r0.x; oA.y = r1.x; oA.z = r2.x; oA.w = r3.x;
        float4 oB; oB.x = r0.y; oB.y = r1.y; oB.z = r2.y; oB.w = r3.y;
        *(float4*)(C + (size_t)(bm + ty * 8 + 2 * p)     * NCAT + bn + lane * 4) = oA;
        *(float4*)(C + (size_t)(bm + ty * 8 + 2 * p + 1) * NCAT + bn + lane * 4) = oB;
    }
}

// ---------------- fused attention: two-phase smem reuse, 2 CTAs per batch -------
// Phase 1: buffers hold q(32) | k(64) -> logits, softmax.
// Phase 2: SAME buffers reloaded with P+bv1(32) | -Q(64) -> u-loop.
// smem = 96*SPITCH + 32*64 floats = 57.5KB -> 2 CTAs/SM.
__global__ __launch_bounds__(512, 2) void attn_u_kernel(const float* __restrict__ qkpq,
                              const float* __restrict__ bv1, float* __restrict__ u)
{
    extern __shared__ float sm[];
    float* b32 = sm;                   // 32 rows: q, then P+bv1
    float* b64 = b32 + 32 * SPITCH;    // 64 rows: k, then -Q
    float* sa  = b64 + 64 * SPITCH;    // 32*64 logits/attn

    const int t  = threadIdx.x;        // 512 threads
    const int b  = blockIdx.x >> 1;
    const int r0 = (blockIdx.x & 1) * 32;
    const size_t base = (size_t)b * NKE;

    // ---- phase-1 loads: q, k
    {
        for (int idx = t; idx < 32 * ND / 4; idx += 512) {
            int row = idx >> 5;
            int col = (idx & 31) << 2;
            const float* src = qkpq + (base + r0 + row) * NCAT + col;
            *(float4*)&b32[row * SPITCH + col] = *(const float4*)(src);           // q
        }
        for (int idx = t; idx < 64 * ND / 4; idx += 512) {
            int row = idx >> 5;
            int col = (idx & 31) << 2;
            const float* src = qkpq + (base + row) * NCAT + col;
            *(float4*)&b64[row * SPITCH + col] = *(const float4*)(src + ND);      // k
        }
    }
    __syncthreads();

    // ---- logits — packed pairwise dot products
    {
        const int i  = t >> 4;
        const int jb = t & 15;
        u64 acc2[4] = {0, 0, 0, 0};
        const float* qrow = b32 + i * SPITCH;
        for (int d = 0; d < ND; d += 4) {
            double2 qd = *(const double2*)(qrow + d);
            u64 q01 = __double_as_longlong(qd.x);
            u64 q23 = __double_as_longlong(qd.y);
#pragma unroll
            for (int jj = 0; jj < 4; jj++) {
                double2 kd = *(const double2*)(b64 + (jb + jj * 16) * SPITCH + d);
                acc2[jj] = fma2(q01, __double_as_longlong(kd.x), acc2[jj]);
                acc2[jj] = fma2(q23, __double_as_longlong(kd.y), acc2[jj]);
            }
        }
#pragma unroll
        for (int jj = 0; jj < 4; jj++) {
            float2 f = unpack2(acc2[jj]);
            sa[i * 64 + jb + jj * 16] = f.x + f.y;
        }
    }
    __syncthreads();   // logits done: sq/sk now dead, sa written

    // ---- softmax (rows in sa) + phase-2 loads (overwrite b32/b64) — disjoint mem
    {
        const int w = t >> 5, lane = t & 31;
#pragma unroll
        for (int r = 0; r < 2; r++) {
            int i = w * 2 + r;
            float v0 = sa[i * 64 + lane], v1 = sa[i * 64 + lane + 32];
            float mx = fmaxf(v0, v1);
            for (int o = 16; o; o >>= 1) mx = fmaxf(mx, __shfl_xor_sync(0xffffffffu, mx, o));
            float e0 = __expf(v0 - mx), e1 = __expf(v1 - mx);
            float s = e0 + e1;
            for (int o = 16; o; o >>= 1) s += __shfl_xor_sync(0xffffffffu, s, o);
            float inv = 1.0f / s;
            sa[i * 64 + lane] = e0 * inv;
            sa[i * 64 + lane + 32] = e1 * inv;
        }
    }
    {
        for (int idx = t; idx < 32 * ND / 4; idx += 512) {
            int row = idx >> 5;
            int col = (idx & 31) << 2;
            const float* src = qkpq + (base + r0 + row) * NCAT + col;
            float4 pv = *(const float4*)(src + 2 * ND);                           // P
            float4 bv = *(const float4*)(bv1 + col);
            pv.x += bv.x; pv.y += bv.y; pv.z += bv.z; pv.w += bv.w;
            *(float4*)&b32[row * SPITCH + col] = pv;
        }
        for (int idx = t; idx < 64 * ND / 4; idx += 512) {
            int row = idx >> 5;
            int col = (idx & 31) << 2;
            const float* src = qkpq + (base + row) * NCAT + col;
            float4 qv = *(const float4*)(src + 3 * ND);                           // Q
            qv.x = -qv.x; qv.y = -qv.y; qv.z = -qv.z; qv.w = -qv.w;
            *(float4*)&b64[row * SPITCH + col] = qv;
        }
    }
    __syncthreads();

    // ---- u accumulate — packed f32x2 gelu chain
    {
        const int w = t >> 5, lane = t & 31;
        const int dl = lane << 2;

        const u64 B4   = pack2(0.019527f, 0.019527f);
        const u64 B3   = pack2(0.00034366f, 0.00034366f);
        const u64 B2   = pack2(0.1151945f, 0.1151945f);
        const u64 B1   = pack2(0.1968561f, 0.1968561f);
        const u64 ONE  = pack2(1.0f, 1.0f);
        const u64 HALF = pack2(0.5f, 0.5f);
        const u64 ABSM = 0x7FFFFFFF7FFFFFFFULL;
        const u64 SGN  = 0x8000000080000000ULL;

#pragma unroll
        for (int ii = 0; ii < 2; ii++) {
            int i = w + ii * 16;
            const double2 Pd = *(const double2*)(b32 + i * SPITCH + dl);
            const u64 P01 = __double_as_longlong(Pd.x);
            const u64 P23 = __double_as_longlong(Pd.y);
            u64 acc01 = 0, acc23 = 0;
            for (int j = 0; j < NKE; j += 4) {
                float4 att = *(const float4*)&sa[i * 64 + j];
#pragma unroll
                for (int jj = 0; jj < 4; jj++) {
                    float aw = (jj == 0) ? att.x : (jj == 1) ? att.y : (jj == 2) ? att.z : att.w;
                    const u64 AW = dup2(aw);
                    const double2 Qd = *(const double2*)(b64 + (j + jj) * SPITCH + dl);
                    u64 x01 = add2(P01, __double_as_longlong(Qd.x));
                    u64 x23 = add2(P23, __double_as_longlong(Qd.y));
                    {
                        u64 ax = x01 & ABSM;
                        u64 p  = fma2(B4, ax, B3);
                        p = fma2(p, ax, B2);
                        p = fma2(p, ax, B1);
                        p = fma2(p, ax, ONE);
                        u64 p2 = mul2(p, p);
                        u64 p4 = mul2(p2, p2);
                        float2 pf = unpack2(p4);
                        u64 r   = pack2(rcpa(pf.x), rcpa(pf.y));
                        u64 hax = mul2(ax, HALF);
                        u64 t1  = fma2(x01, HALF, hax);      // relu(x)
                        u64 nh  = hax ^ SGN;                 // -0.5|x| (alu pipe)
                        u64 g   = fma2(nh, r, t1);
                        acc01 = fma2(AW, g, acc01);
                    }
                    {
                        u64 ax = x23 & ABSM;
                        u64 p  = fma2(B4, ax, B3);
                        p = fma2(p, ax, B2);
                        p = fma2(p, ax, B1);
                        p = fma2(p, ax, ONE);
                        u64 p2 = mul2(p, p);
                        u64 p4 = mul2(p2, p2);
                        float2 pf = unpack2(p4);
                        u64 r   = pack2(rcpa(pf.x), rcpa(pf.y));
                        u64 hax = mul2(ax, HALF);
                        u64 t1  = fma2(x23, HALF, hax);
                        u64 nh  = hax ^ SGN;
                        u64 g   = fma2(nh, r, t1);
                        acc23 = fma2(AW, g, acc23);
                    }
                }
            }
            float2 lo = unpack2(acc01);
            float2 hi = unpack2(acc23);
            float4 o; o.x = lo.x; o.y = lo.y; o.z = hi.x; o.w = hi.y;
            *(float4*)(u + (base + r0 + i) * ND + dl) = o;
        }
    }
}

// ---------------- persistent weights-resident fused MLP (R12 version) -----------
__device__ __forceinline__ void gemm_res(const float* __restrict__ Wb,
                                         const float* __restrict__ uT,
                                         int ty, int lane, u64 acc2[2][4])
{
    const float* ap = uT + ty * 4;
    const float* bp = Wb + lane * 4;

    double2 a0 = *(const double2*)(ap);
    float4  c0 = *(const float4*)(bp);
    double2 a1 = *(const double2*)(ap + UTP);
    float4  c1 = *(const float4*)(bp + 128);

#pragma unroll 8
    for (int kk = 0; kk < 128; kk += 2) {
        const int nk = (kk + 2 < 128) ? kk + 2 : 0;   // clamp; values unused last iter
        double2 an0 = *(const double2*)(ap + nk * UTP);
        float4  cn0 = *(const float4*)(bp + nk * 128);
        double2 an1 = *(const double2*)(ap + (nk + 1) * UTP);
        float4  cn1 = *(const float4*)(bp + (nk + 1) * 128);

        {
            u64 a01 = __double_as_longlong(a0.x);
            u64 a23 = __double_as_longlong(a0.y);
            u64 b0 = dup2(c0.x), b1 = dup2(c0.y), b2 = dup2(c0.z), b3 = dup2(c0.w);
            acc2[0][0] = fma2(a01, b0, acc2[0][0]); acc2[0][1] = fma2(a01, b1, acc2[0][1]);
            acc2[0][2] = fma2(a01, b2, acc2[0][2]); acc2[0][3] = fma2(a01, b3, acc2[0][3]);
            acc2[1][0] = fma2(a23, b0, acc2[1][0]); acc2[1][1] = fma2(a23, b1, acc2[1][1]);
            acc2[1][2] = fma2(a23, b2, acc2[1][2]); acc2[1][3] = fma2(a23, b3, acc2[1][3]);
        }
        {
            u64 a01 = __double_as_longlong(a1.x);
            u64 a23 = __double_as_longlong(a1.y);
            u64 b0 = dup2(c1.x), b1 = dup2(c1.y), b2 = dup2(c1.z), b3 = dup2(c1.w);
            acc2[0][0] = fma2(a01, b0, acc2[0][0]); acc2[0][1] = fma2(a01, b1, acc2[0][1]);
            acc2[0][2] = fma2(a01, b2, acc2[0][2]); acc2[0][3] = fma2(a01, b3, acc2[0][3]);
            acc2[1][0] = fma2(a23, b0, acc2[1][0]); acc2[1][1] = fma2(a23, b1, acc2[1][1]);
            acc2[1][2] = fma2(a23, b2, acc2[1][2]); acc2[1][3] = fma2(a23, b3, acc2[1][3]);
        }
        a0 = an0; c0 = cn0; a1 = an1; c1 = cn1;
    }
}

__device__ __forceinline__ void unpack_acc(const u64 acc2[2][4], float acc[4][4]) {
#pragma unroll
    for (int p = 0; p < 2; p++)
#pragma unroll
        for (int j = 0; j < 4; j++) {
            float2 f = unpack2(acc2[p][j]);
            acc[2 * p][j]     = f.x;
            acc[2 * p + 1][j] = f.y;
        }
}

__global__ __launch_bounds__(256) void fused_mlp(
    const float* __restrict__ u,   const float* __restrict__ xa,
    const float* __restrict__ Wv2, const float* __restrict__ bv2,
    const float* __restrict__ lng, const float* __restrict__ lnb,
    const float* __restrict__ Wm1, const float* __restrict__ bm1,
    const float* __restrict__ Wm2, const float* __restrict__ bm2,
    float* __restrict__ xo)
{
    extern __shared__ float sm[];
    float* Wall = sm;                 // 3 * 16384 = 49152
    float* uT   = Wall + 3 * 16384;   // 128 * 36  = 4608
    float* hs   = uT + 128 * UTP;     // 32 * 128  = 4096   total 57856 f = 226KB

    const int t    = threadIdx.x;     // 256
    const int ty   = t >> 5;          // warp 0..7 -> rows ty*4..+3
    const int lane = t & 31;          // cols lane*4..+3
    const int cl   = lane << 2;

    // ---- load all three weights once
    {
        const float* srcs[3] = {Wv2, Wm1, Wm2};
#pragma unroll
        for (int w = 0; w < 3; w++) {
            float4* dst = (float4*)(Wall + w * 16384);
            const float4* src = (const float4*)srcs[w];
            for (int i = t; i < 4096; i += 256) dst[i] = src[i];
        }
    }
    __syncthreads();

    float4 gg = *(const float4*)(lng + cl);
    float4 lb = *(const float4*)(lnb + cl);
    float4 b1v = *(const float4*)(bv2 + cl);
    float4 b2v = *(const float4*)(bm1 + cl);
    float4 b3v = *(const float4*)(bm2 + cl);

    for (int tile = blockIdx.x; tile < NTILES; tile += PGRID) {
        const int r0 = tile * 32;

        // stage u transposed
        for (int idx = t; idx < 32 * ND; idx += 256) {
            int r = idx >> 7, k = idx & 127;
            uT[k * UTP + r] = u[(size_t)(r0 + r) * ND + k];
        }
        __syncthreads();

        u64 acc2[2][4];
        float acc[4][4];

        // ---- GEMM1: h2 = u@Wv2 + bv2 + x ; LN -> hs
#pragma unroll
        for (int p = 0; p < 2; p++)
#pragma unroll
            for (int j = 0; j < 4; j++) acc2[p][j] = 0;
        gemm_res(Wall, uT, ty, lane, acc2);
        unpack_acc(acc2, acc);
        {
#pragma unroll
            for (int i = 0; i < 4; i++) {
                int r = ty * 4 + i;
                float4 xv = *(const float4*)(xa + (size_t)(r0 + r) * ND + cl);
                float v0 = acc[i][0] + b1v.x + xv.x;
                float v1 = acc[i][1] + b1v.y + xv.y;
                float v2 = acc[i][2] + b1v.z + xv.z;
                float v3 = acc[i][3] + b1v.w + xv.w;
                float s  = v0 + v1 + v2 + v3;
                float s2 = v0 * v0 + v1 * v1 + v2 * v2 + v3 * v3;
                for (int o = 16; o; o >>= 1) {
                    s  += __shfl_xor_sync(0xffffffffu, s, o);
                    s2 += __shfl_xor_sync(0xffffffffu, s2, o);
                }
                float mu  = s * (1.0f / ND);
                float var = s2 * (1.0f / ND) - mu * mu;
                float inv = rsqrtf(var + 1e-5f);
                float4 o4;
                o4.x = (v0 - mu) * inv * gg.x + lb.x;
                o4.y = (v1 - mu) * inv * gg.y + lb.y;
                o4.z = (v2 - mu) * inv * gg.z + lb.z;
                o4.w = (v3 - mu) * inv * gg.w + lb.w;
                *(float4*)&hs[r * 128 + cl] = o4;
            }
        }
        __syncthreads();
        for (int idx = t; idx < 32 * ND; idx += 256) {
            int r = idx >> 7, k = idx & 127;
            uT[k * UTP + r] = hs[r * 128 + k];
        }
        __syncthreads();

        // ---- GEMM2: t = gelu(ln@Wm1 + bm1) -> hs
#pragma unroll
        for (int p = 0; p < 2; p++)
#pragma unroll
            for (int j = 0; j < 4; j++) acc2[p][j] = 0;
        gemm_res(Wall + 16384, uT, ty, lane, acc2);
        unpack_acc(acc2, acc);
        {
#pragma unroll
            for (int i = 0; i < 4; i++) {
                int r = ty * 4 + i;
                float4 o4;
                o4.x = gelu_fast(acc[i][0] + b2v.x);
                o4.y = gelu_fast(acc[i][1] + b2v.y);
                o4.z = gelu_fast(acc[i][2] + b2v.z);
                o4.w = gelu_fast(acc[i][3] + b2v.w);
                *(float4*)&hs[r * 128 + cl] = o4;
            }
        }
        __syncthreads();
        for (int idx = t; idx < 32 * ND; idx += 256) {
            int r = idx >> 7, k = idx & 127;
            uT[k * UTP + r] = hs[r * 128 + k];
        }
        __syncthreads();

        // ---- GEMM3: out = x + t@Wm2 + bm2 -> global
#pragma unroll
        for (int p = 0; p < 2; p++)
#pragma unroll
            for (int j = 0; j < 4; j++) acc2[p][j] = 0;
        gemm_res(Wall + 32768, uT, ty, lane, acc2);
        unpack_acc(acc2, acc);
        {
#pragma unroll
            for (int i = 0; i < 4; i++) {
                int r = ty * 4 + i;
                float4 xv = *(const float4*)(xa + (size_t)(r0 + r) * ND + cl);
                float4 o4;
                o4.x = acc[i][0] + b3v.x + xv.x;
                o4.y = acc[i][1] + b3v.y + xv.y;
                o4.z = acc[i][2] + b3v.z + xv.z;
                o4.w = acc[i][3] + b3v.w + xv.w;
                *(float4*)(xo + (size_t)(r0 + r) * ND + cl) = o4;
            }
        }
        __syncthreads();   // protect uT before next tile restages
    }
}

// ---------------- fused head: pool + proj(gelu) + mu/sp projections -------------
__global__ void head_kernel(const float* __restrict__ x,
                            const float* __restrict__ Wp,  const float* __restrict__ bp,
                            const float* __restrict__ Wmu, const float* __restrict__ bmu,
                            const float* __restrict__ Wsp, const float* __restrict__ bsp,
                            float* __restrict__ out)
{
    __shared__ float spool[ND];
    __shared__ float sproj[NS];
    const int b = blockIdx.x;
    const int t = threadIdx.x;   // 128 threads

    {
        float s = 0.f;
        const float* p = x + (size_t)b * NKE * ND + t;
        for (int i = 0; i < NKE; i++) s += p[i * ND];
        spool[t] = s;
    }
    __syncthreads();
    {
        float acc = bp[t];
        for (int d = 0; d < ND; d++) acc += spool[d] * Wp[d * NS + t];
        sproj[t] = gelu_fast(acc);
    }
    __syncthreads();
    {
        float amu = bmu[t], asp = bsp[t];
        for (int s = 0; s < NS; s++) {
            float f = sproj[s];
            amu += f * Wmu[s * NS + t];
            asp += f * Wsp[s * NS + t];
        }
        out[(size_t)b * NS + t] = amu;
        out[(size_t)NB * NS + (size_t)b * NS + t] = asp;
    }
}

// ---------------- launch --------------------------------------------------------
extern "C" void kernel_launch(void* const* d_in, const int* in_sizes, int n_in,
                              void* d_out, int out_size)
{
    const float* x_in = (const float*)d_in[0];
    const float* Wk   = (const float*)d_in[1];
    const float* Wq   = (const float*)d_in[2];
    const float* Wv1  = (const float*)d_in[3];
    const float* bv1  = (const float*)d_in[4];
    const float* Wv2  = (const float*)d_in[5];
    const float* bv2  = (const float*)d_in[6];
    const float* lng  = (const float*)d_in[7];
    const float* lnb  = (const float*)d_in[8];
    const float* Wm1  = (const float*)d_in[9];
    const float* bm1  = (const float*)d_in[10];
    const float* Wm2  = (const float*)d_in[11];
    const float* bm2  = (const float*)d_in[12];
    const float* Wp   = (const float*)d_in[13];
    const float* bp   = (const float*)d_in[14];
    const float* Wmu  = (const float*)d_in[15];
    const float* bmu  = (const float*)d_in[16];
    const float* Wsp  = (const float*)d_in[17];
    const float* bsp  = (const float*)d_in[18];
    float* out = (float*)d_out;

    float *px, *pqkpq, *pu, *pwcat;
    cudaGetSymbolAddress((void**)&px,    g_x);
    cudaGetSymbolAddress((void**)&pqkpq, g_qkpq);
    cudaGetSymbolAddress((void**)&pu,    g_u);
    cudaGetSymbolAddress((void**)&pwcat, g_wcat);

    const int SMEM_AU = (96 * SPITCH + 32 * NKE) * (int)sizeof(float);    // ~57.5KB
    cudaFuncSetAttribute(attn_u_kernel, cudaFuncAttributeMaxDynamicSharedMemorySize, SMEM_AU);
    const int SMEM_P = (3 * 16384 + 128 * UTP + 32 * 128) * (int)sizeof(float);  // 226KB
    cudaFuncSetAttribute(fused_mlp, cudaFuncAttributeMaxDynamicSharedMemorySize, SMEM_P);

    const float scale = 1.0f / sqrtf((float)ND);

    prep_wcat<<<dim3(256, NL), 256>>>(Wq, Wk, Wv1, pwcat, scale);

    dim3 gq(MROWS / 64, NCAT / 128);    // (128, 4) = 512 CTAs
    for (int l = 0; l < NL; l++) {
        const float* Wcat_l = pwcat + (size_t)l * ND * NCAT;
        const float* bv1_l = bv1 + (size_t)l * ND;
        const float* Wv2_l = Wv2 + (size_t)l * ND * ND;
        const float* bv2_l = bv2 + (size_t)l * ND;
        const float* g_l   = lng + (size_t)l * ND;
        const float* b_l   = lnb + (size_t)l * ND;
        const float* Wm1_l = Wm1 + (size_t)l * ND * ND;
        const float* bm1_l = bm1 + (size_t)l * ND;
        const float* Wm2_l = Wm2 + (size_t)l * ND * ND;
        const float* bm2_l = bm2 + (size_t)l * ND;

        const float* xa = (l == 0) ? x_in : px;

        gemm_qkpq<<<gq, 256>>>(xa, Wcat_l, pqkpq);
        attn_u_kernel<<<NB * 2, 512, SMEM_AU>>>(pqkpq, bv1_l, pu);
        fused_mlp<<<PGRID, 256, SMEM_P>>>(pu, xa, Wv2_l, bv2_l, g_l, b_l,
                                          Wm1_l, bm1_l, Wm2_l, bm2_l, px);
    }

    head_kernel<<<NB, ND>>>(px, Wp, bp, Wmu, bmu, Wsp, bsp, out);
}